// round 7
// baseline (speedup 1.0000x reference)
#include <cuda_runtime.h>
#include <cuda_bf16.h>
#include <cstdint>

// GumbelSoftmaxVectorQuantizer — round 7: bf16 main + fp8(e4m3) cross terms
//   logits = Ah*Bh (bf16, exact)  +  (256Al*16Bh + 8Ah*512Bl)/4096 (fp8)
//   2 bf16 + 2 fp8 MMAs per k32 vs 6 bf16 before -> 1.5x fewer issue slots.

static constexpr int Mx = 16384;
static constexpr int Kx = 1024;
static constexpr int Nx = 4096;
static constexpr int Vx = 1024;
static constexpr int Dx = 128;
static constexpr float INV_TAU = 0.5f;
static constexpr float SAL = 256.f, SAH = 8.f, SBH = 16.f, SBL = 512.f;
static constexpr float INV_S = 1.f / 4096.f;   // 1/(SAL*SBH) = 1/(SAH*SBL)

__device__ float g_logits[(size_t)Mx * Nx];
__device__ unsigned short g_Ah[(size_t)Mx * Kx];   // bf16 [M][K]
__device__ unsigned char  g_A8[(size_t)Mx * Kx * 2]; // [M][2K]: per k32: [256*Al | 8*Ah]
__device__ unsigned short g_Bh[(size_t)Nx * Kx];   // bf16 [N][K] = W^T
__device__ unsigned char  g_B8[(size_t)Nx * Kx * 2]; // [N][2K]: per k32: [16*Bh | 512*Bl]

__device__ __forceinline__ uint32_t smem_u32(const void* p) {
    uint32_t a;
    asm("{ .reg .u64 t; cvta.to.shared.u64 t, %1; cvt.u32.u64 %0, t; }" : "=r"(a) : "l"(p));
    return a;
}
__device__ __forceinline__ unsigned short cvt_e4m3x2(float hi, float lo) {
    unsigned short r;
    asm("cvt.rn.satfinite.e4m3x2.f32 %0, %1, %2;" : "=h"(r) : "f"(hi), "f"(lo));
    return r;
}

// ---------------- K0a: split A ----------------
__global__ __launch_bounds__(256)
void split_a_kernel(const float* __restrict__ A) {
    const size_t idx = ((size_t)blockIdx.x * 256 + threadIdx.x) * 8;
    if (idx >= (size_t)Mx * Kx) return;
    const int m = (int)(idx >> 10);
    const int k = (int)(idx & 1023);
    float4 a0 = *(const float4*)&A[idx];
    float4 a1 = *(const float4*)&A[idx + 4];
    float v[8] = {a0.x, a0.y, a0.z, a0.w, a1.x, a1.y, a1.z, a1.w};
    unsigned short h[8];
    float lo[8], hi[8];
#pragma unroll
    for (int t = 0; t < 8; t++) {
        __nv_bfloat16 hb = __float2bfloat16(v[t]);
        h[t] = __bfloat16_as_ushort(hb);
        hi[t] = __bfloat162float(hb);
        lo[t] = v[t] - hi[t];
    }
    uint4 uh;
    uh.x = h[0] | ((uint32_t)h[1] << 16); uh.y = h[2] | ((uint32_t)h[3] << 16);
    uh.z = h[4] | ((uint32_t)h[5] << 16); uh.w = h[6] | ((uint32_t)h[7] << 16);
    *(uint4*)&g_Ah[idx] = uh;

    unsigned short pl[4], ph[4];
#pragma unroll
    for (int t = 0; t < 4; t++) {
        pl[t] = cvt_e4m3x2(lo[2 * t + 1] * SAL, lo[2 * t] * SAL);
        ph[t] = cvt_e4m3x2(hi[2 * t + 1] * SAH, hi[2 * t] * SAH);
    }
    const int q = k >> 5, rem = k & 31;
    const size_t b8 = (size_t)m * 2048 + q * 64 + rem;
    unsigned long long wl = (unsigned long long)pl[0] | ((unsigned long long)pl[1] << 16)
                          | ((unsigned long long)pl[2] << 32) | ((unsigned long long)pl[3] << 48);
    unsigned long long wh = (unsigned long long)ph[0] | ((unsigned long long)ph[1] << 16)
                          | ((unsigned long long)ph[2] << 32) | ((unsigned long long)ph[3] << 48);
    *(unsigned long long*)&g_A8[b8]      = wl;   // 256*Al
    *(unsigned long long*)&g_A8[b8 + 32] = wh;   // 8*Ah
}

// ---------------- K0b: split + transpose W ----------------
__global__ __launch_bounds__(256)
void split_w_kernel(const float* __restrict__ W) {
    __shared__ float s[64][65];
    const int ct = blockIdx.y;
    const int n0 = blockIdx.x * 64;
    const int k0 = ct * 64;
    const int tid = threadIdx.x;
    for (int i = tid; i < 1024; i += 256) {
        const int kk = i >> 4, n4 = (i & 15) << 2;
        float4 w = *(const float4*)&W[(size_t)(k0 + kk) * Nx + n0 + n4];
        s[kk][n4] = w.x; s[kk][n4 + 1] = w.y; s[kk][n4 + 2] = w.z; s[kk][n4 + 3] = w.w;
    }
    __syncthreads();
    for (int i = tid; i < 512; i += 256) {
        const int nl = i >> 3, j = (i & 7) << 3;   // 8 consecutive k
        unsigned short h[8];
        float lo[8], hi[8];
#pragma unroll
        for (int t = 0; t < 8; t++) {
            float a = s[j + t][nl];
            __nv_bfloat16 hb = __float2bfloat16(a);
            h[t] = __bfloat16_as_ushort(hb);
            hi[t] = __bfloat162float(hb);
            lo[t] = a - hi[t];
        }
        const size_t o = (size_t)(n0 + nl) * Kx + k0 + j;
        uint4 uh;
        uh.x = h[0] | ((uint32_t)h[1] << 16); uh.y = h[2] | ((uint32_t)h[3] << 16);
        uh.z = h[4] | ((uint32_t)h[5] << 16); uh.w = h[6] | ((uint32_t)h[7] << 16);
        *(uint4*)&g_Bh[o] = uh;

        unsigned short phh[4], pll[4];
#pragma unroll
        for (int t = 0; t < 4; t++) {
            phh[t] = cvt_e4m3x2(hi[2 * t + 1] * SBH, hi[2 * t] * SBH);
            pll[t] = cvt_e4m3x2(lo[2 * t + 1] * SBL, lo[2 * t] * SBL);
        }
        const int kg = k0 + j;
        const int q = kg >> 5, rem = kg & 31;
        const size_t b8 = (size_t)(n0 + nl) * 2048 + q * 64 + rem;
        unsigned long long wh = (unsigned long long)phh[0] | ((unsigned long long)phh[1] << 16)
                              | ((unsigned long long)phh[2] << 32) | ((unsigned long long)phh[3] << 48);
        unsigned long long wl = (unsigned long long)pll[0] | ((unsigned long long)pll[1] << 16)
                              | ((unsigned long long)pll[2] << 32) | ((unsigned long long)pll[3] << 48);
        *(unsigned long long*)&g_B8[b8]      = wh;   // 16*Bh
        *(unsigned long long*)&g_B8[b8 + 32] = wl;   // 512*Bl
    }
}

// ---------------- K1: GEMM ----------------
static constexpr int BK = 32;
static constexpr int STAGES = 4;
static constexpr int RB = 80;                       // bytes per smem row (all operands)
static constexpr int OFF_AH = 0;
static constexpr int OFF_BH = 10240;
static constexpr int OFF_A8 = 20480;
static constexpr int OFF_B8 = 30720;
static constexpr int STAGE_BYTES = 40960;
static constexpr int SMEM_BYTES = STAGES * STAGE_BYTES;  // 163840
static constexpr int NCHUNK = Kx / BK;
static constexpr int NTHREADS = 512;

__device__ __forceinline__ void cp16(uint32_t dst, const void* src) {
    asm volatile("cp.async.cg.shared.global [%0], [%1], 16;" :: "r"(dst), "l"(src) : "memory");
}
__device__ __forceinline__ void cp_commit() {
    asm volatile("cp.async.commit_group;" ::: "memory");
}
__device__ __forceinline__ void cp_wait2() {
    asm volatile("cp.async.wait_group 2;" ::: "memory");
}
__device__ __forceinline__ void ldsm4(uint32_t& r0, uint32_t& r1, uint32_t& r2, uint32_t& r3,
                                      uint32_t addr) {
    asm volatile("ldmatrix.sync.aligned.m8n8.x4.shared.b16 {%0,%1,%2,%3}, [%4];"
                 : "=r"(r0), "=r"(r1), "=r"(r2), "=r"(r3) : "r"(addr));
}
__device__ __forceinline__ void mma_bf16(float* c, const uint32_t* a, const uint32_t* b) {
    asm volatile(
        "mma.sync.aligned.m16n8k16.row.col.f32.bf16.bf16.f32 "
        "{%0,%1,%2,%3}, {%4,%5,%6,%7}, {%8,%9}, {%0,%1,%2,%3};"
        : "+f"(c[0]), "+f"(c[1]), "+f"(c[2]), "+f"(c[3])
        : "r"(a[0]), "r"(a[1]), "r"(a[2]), "r"(a[3]), "r"(b[0]), "r"(b[1]));
}
__device__ __forceinline__ void mma_fp8(float* c, const uint32_t* a, const uint32_t* b) {
    asm volatile(
        "mma.sync.aligned.m16n8k32.row.col.f32.e4m3.e4m3.f32 "
        "{%0,%1,%2,%3}, {%4,%5,%6,%7}, {%8,%9}, {%0,%1,%2,%3};"
        : "+f"(c[0]), "+f"(c[1]), "+f"(c[2]), "+f"(c[3])
        : "r"(a[0]), "r"(a[1]), "r"(a[2]), "r"(a[3]), "r"(b[0]), "r"(b[1]));
}

__global__ __launch_bounds__(NTHREADS, 1)
void gemm_kernel(const float* __restrict__ bias, const float* __restrict__ gum) {
    extern __shared__ char smem[];
    const uint32_t sbase = smem_u32(smem);
    const int tid  = threadIdx.x;
    const int lane = tid & 31;
    const int wid  = tid >> 5;
    const int wm   = wid >> 2;
    const int wn   = wid & 3;
    const int bm   = blockIdx.y * 128;
    const int bn   = blockIdx.x * 128;

    const unsigned short* srcAh = g_Ah + (size_t)bm * Kx;
    const unsigned short* srcBh = g_Bh + (size_t)bn * Kx;
    const unsigned char*  srcA8 = g_A8 + (size_t)bm * 2048;
    const unsigned char*  srcB8 = g_B8 + (size_t)bn * 2048;

    auto issue_stage = [&](int chunk) {
        const int s = chunk & (STAGES - 1);
        const uint32_t stb = sbase + s * STAGE_BYTES;
        const int r = (tid >> 2) & 127;
        const int c = tid & 3;
        const uint32_t doff = (uint32_t)(r * RB + c * 16);
        cp16(stb + OFF_AH + doff, srcAh + (size_t)r * Kx + chunk * 32 + c * 8);
        cp16(stb + OFF_BH + doff, srcBh + (size_t)r * Kx + chunk * 32 + c * 8);
        cp16(stb + OFF_A8 + doff, srcA8 + (size_t)r * 2048 + chunk * 64 + c * 16);
        cp16(stb + OFF_B8 + doff, srcB8 + (size_t)r * 2048 + chunk * 64 + c * 16);
        cp_commit();
    };

    float acc[2][4][4];    // bf16 main
    float acc8[2][4][4];   // fp8 cross (scaled by 4096)
#pragma unroll
    for (int i = 0; i < 2; i++)
#pragma unroll
        for (int j = 0; j < 4; j++)
#pragma unroll
            for (int q = 0; q < 4; q++) { acc[i][j][q] = 0.f; acc8[i][j][q] = 0.f; }

    issue_stage(0); issue_stage(1); issue_stage(2);

    const int lrow = lane & 15;
    const int lhalf = lane >> 4;

#pragma unroll 1
    for (int ch = 0; ch < NCHUNK; ch++) {
        cp_wait2();
        __syncthreads();
        if (ch + 3 < NCHUNK) issue_stage(ch + 3);

        const uint32_t stb = sbase + (ch & (STAGES - 1)) * STAGE_BYTES;
        const uint32_t aho = stb + OFF_AH;
        const uint32_t bho = stb + OFF_BH;
        const uint32_t a8o = stb + OFF_A8;
        const uint32_t b8o = stb + OFF_B8;

        // ---- bf16 main: 2 k16 halves ----
#pragma unroll
        for (int ks = 0; ks < 2; ks++) {
            uint32_t ah[2][4], bh[4][2];
#pragma unroll
            for (int mf = 0; mf < 2; mf++) {
                const int row = wm * 32 + mf * 16 + lrow;
                const uint32_t off = (uint32_t)(row * RB + (ks * 16 + lhalf * 8) * 2);
                ldsm4(ah[mf][0], ah[mf][1], ah[mf][2], ah[mf][3], aho + off);
            }
#pragma unroll
            for (int np = 0; np < 2; np++) {
                const int row = wn * 32 + np * 16 + lrow;
                const uint32_t off = (uint32_t)(row * RB + (ks * 16 + lhalf * 8) * 2);
                uint32_t r0, r1, r2, r3;
                ldsm4(r0, r1, r2, r3, bho + off);
                bh[2 * np][0] = r0; bh[2 * np][1] = r2;
                bh[2 * np + 1][0] = r1; bh[2 * np + 1][1] = r3;
            }
#pragma unroll
            for (int mf = 0; mf < 2; mf++)
#pragma unroll
                for (int nf = 0; nf < 4; nf++)
                    mma_bf16(acc[mf][nf], ah[mf], bh[nf]);
        }

        // ---- fp8 cross: 2 halves (h=0: 256Al*16Bh, h=1: 8Ah*512Bl) ----
#pragma unroll
        for (int h = 0; h < 2; h++) {
            uint32_t a8[2][4], b8[4][2];
#pragma unroll
            for (int mf = 0; mf < 2; mf++) {
                const int row = wm * 32 + mf * 16 + lrow;
                const uint32_t off = (uint32_t)(row * RB + h * 32 + lhalf * 16);
                ldsm4(a8[mf][0], a8[mf][1], a8[mf][2], a8[mf][3], a8o + off);
            }
#pragma unroll
            for (int np = 0; np < 2; np++) {
                const int row = wn * 32 + np * 16 + lrow;
                const uint32_t off = (uint32_t)(row * RB + h * 32 + lhalf * 16);
                uint32_t r0, r1, r2, r3;
                ldsm4(r0, r1, r2, r3, b8o + off);
                b8[2 * np][0] = r0; b8[2 * np][1] = r2;
                b8[2 * np + 1][0] = r1; b8[2 * np + 1][1] = r3;
            }
#pragma unroll
            for (int mf = 0; mf < 2; mf++)
#pragma unroll
                for (int nf = 0; nf < 4; nf++)
                    mma_fp8(acc8[mf][nf], a8[mf], b8[nf]);
        }
        __syncthreads();
    }

    // epilogue: (main + cross/4096 + bias + gumbel) * INV_TAU
    const int er = lane >> 2;
    const int ec = (lane & 3) * 2;
#pragma unroll
    for (int mf = 0; mf < 2; mf++) {
#pragma unroll
        for (int nf = 0; nf < 4; nf++) {
            const int col = bn + wn * 32 + nf * 8 + ec;
            const float2 bb = *(const float2*)&bias[col];
#pragma unroll
            for (int h = 0; h < 2; h++) {
                const int row = bm + wm * 32 + mf * 16 + er + h * 8;
                const size_t go = (size_t)row * Nx + col;
                const float2 g = *(const float2*)&gum[go];
                float2 o;
                o.x = (acc[mf][nf][2 * h]     + acc8[mf][nf][2 * h]     * INV_S + bb.x + g.x) * INV_TAU;
                o.y = (acc[mf][nf][2 * h + 1] + acc8[mf][nf][2 * h + 1] * INV_S + bb.y + g.y) * INV_TAU;
                *(float2*)&g_logits[go] = o;
            }
        }
    }
}

// ---------------- K2: softmax + argmax(top2 + exact fixup) ----------------
__global__ __launch_bounds__(128)
void softmax_kernel(const int*   __restrict__ pads,
                    const float* __restrict__ codebook,
                    const float* __restrict__ A,
                    const float* __restrict__ W,
                    const float* __restrict__ bias,
                    const float* __restrict__ gum,
                    float*       __restrict__ ids_out,
                    float*       __restrict__ quant_out,
                    float*       __restrict__ probs_out)
{
    const int grp  = blockIdx.x;
    const int row  = grp >> 2;
    const int g    = grp & 3;
    const int tid  = threadIdx.x;
    const int lane = tid & 31;
    const int warp = tid >> 5;

    const float* base = g_logits + (size_t)grp * Vx;

    float v[8];
    *(float4*)&v[0] = *(const float4*)&base[tid * 8];
    *(float4*)&v[4] = *(const float4*)&base[tid * 8 + 4];

    float m1 = v[0], m2 = -3.4e38f;
    int i1 = tid * 8, i2 = -1;
#pragma unroll
    for (int j = 1; j < 8; j++) {
        const int ii = tid * 8 + j;
        if (v[j] > m1) { m2 = m1; i2 = i1; m1 = v[j]; i1 = ii; }
        else if (v[j] > m2) { m2 = v[j]; i2 = ii; }
    }
#pragma unroll
    for (int off = 16; off > 0; off >>= 1) {
        float o1 = __shfl_down_sync(0xffffffffu, m1, off);
        int   oi1 = __shfl_down_sync(0xffffffffu, i1, off);
        float o2 = __shfl_down_sync(0xffffffffu, m2, off);
        int   oi2 = __shfl_down_sync(0xffffffffu, i2, off);
        if (o1 > m1 || (o1 == m1 && oi1 < i1)) {
            float t2 = (m1 > o2 || (m1 == o2 && i1 < oi2)) ? m1 : o2;
            int   ti2 = (m1 > o2 || (m1 == o2 && i1 < oi2)) ? i1 : oi2;
            m1 = o1; i1 = oi1; m2 = t2; i2 = ti2;
        } else {
            if (o1 > m2 || (o1 == m2 && oi1 < i2)) { m2 = o1; i2 = oi1; }
        }
    }

    __shared__ float sw1[4], sw2[4], ssum[4];
    __shared__ int   si1[4], si2[4];
    __shared__ float red_m, red_s, sfix[2];
    __shared__ int   red_i, cand1, cand2, need_fix;

    if (lane == 0) { sw1[warp] = m1; si1[warp] = i1; sw2[warp] = m2; si2[warp] = i2; }
    __syncthreads();
    if (tid == 0) {
        float b1 = sw1[0], b2 = sw2[0]; int j1 = si1[0], j2 = si2[0];
        for (int w = 1; w < 4; w++) {
            float o1 = sw1[w], o2 = sw2[w]; int oi1 = si1[w], oi2 = si2[w];
            if (o1 > b1 || (o1 == b1 && oi1 < j1)) {
                float t2 = (b1 > o2 || (b1 == o2 && j1 < oi2)) ? b1 : o2;
                int   ti2 = (b1 > o2 || (b1 == o2 && j1 < oi2)) ? j1 : oi2;
                b1 = o1; j1 = oi1; b2 = t2; j2 = ti2;
            } else if (o1 > b2 || (o1 == b2 && oi1 < j2)) { b2 = o1; j2 = oi1; }
        }
        red_m = b1; red_i = j1; cand1 = j1; cand2 = j2;
        need_fix = (b1 - b2 < 3e-3f) ? 1 : 0;
    }
    __syncthreads();

    const int pad = pads[row];

    if (need_fix && !pad) {
        const float* arow = A + (size_t)row * Kx;
        for (int cidx = 0; cidx < 2; cidx++) {
            const int vv = (cidx == 0) ? cand1 : cand2;
            const int col = (g << 10) + vv;
            float part = 0.f;
#pragma unroll
            for (int j = 0; j < 8; j++) {
                const int k = tid * 8 + j;
                part = fmaf(arow[k], W[(size_t)k * Nx + col], part);
            }
#pragma unroll
            for (int off = 16; off > 0; off >>= 1)
                part += __shfl_down_sync(0xffffffffu, part, off);
            if (lane == 0) ssum[warp] = part;
            __syncthreads();
            if (tid == 0) {
                float tot = ssum[0] + ssum[1] + ssum[2] + ssum[3];
                sfix[cidx] = (tot + bias[col] + gum[(size_t)grp * Vx + vv]) * INV_TAU;
            }
            __syncthreads();
        }
        if (tid == 0) {
            const float v1 = sfix[0], v2 = sfix[1];
            red_i = (v2 > v1 || (v2 == v1 && cand2 < cand1)) ? cand2 : cand1;
        }
        __syncthreads();
    }

    const float mx = red_m;
    float e[8]; float s = 0.f;
#pragma unroll
    for (int j = 0; j < 8; j++) { e[j] = __expf(v[j] - mx); s += e[j]; }
#pragma unroll
    for (int off = 16; off > 0; off >>= 1)
        s += __shfl_down_sync(0xffffffffu, s, off);
    if (lane == 0) ssum[warp] = s;
    __syncthreads();
    if (tid == 0) red_s = ssum[0] + ssum[1] + ssum[2] + ssum[3];
    __syncthreads();

    const float inv = pad ? 0.f : (1.f / red_s);
    float4 p0, p1;
    p0.x = e[0] * inv; p0.y = e[1] * inv; p0.z = e[2] * inv; p0.w = e[3] * inv;
    p1.x = e[4] * inv; p1.y = e[5] * inv; p1.z = e[6] * inv; p1.w = e[7] * inv;
    *(float4*)&probs_out[(size_t)grp * Vx + tid * 8]     = p0;
    *(float4*)&probs_out[(size_t)grp * Vx + tid * 8 + 4] = p1;

    const int id = red_i;
    const float q = pad ? 0.f : codebook[(((g << 10) + id) << 7) + tid];
    quant_out[(size_t)row * (4 * Dx) + g * Dx + tid] = q;
    if (tid == 0) ids_out[grp] = pad ? -1.0f : (float)id;
}

// ---------------- launch ----------------
extern "C" void kernel_launch(void* const* d_in, const int* in_sizes, int n_in,
                              void* d_out, int out_size)
{
    const float* inputs = (const float*)d_in[0];
    const int*   pads   = (const int*)  d_in[1];
    const float* gum    = (const float*)d_in[2];
    const float* W      = (const float*)d_in[3];
    const float* bias   = (const float*)d_in[4];
    const float* cb     = (const float*)d_in[5];

    float* out       = (float*)d_out;
    float* ids_out   = out;
    float* quant_out = out + (size_t)Mx * 4;
    float* probs_out = quant_out + (size_t)Mx * 4 * Dx;

    cudaFuncSetAttribute(gemm_kernel, cudaFuncAttributeMaxDynamicSharedMemorySize, SMEM_BYTES);

    split_a_kernel<<<(Mx * Kx / 8 + 255) / 256, 256>>>(inputs);
    dim3 wg(Nx / 64, Kx / 64);
    split_w_kernel<<<wg, 256>>>(W);
    dim3 grid(Nx / 128, Mx / 128);
    gemm_kernel<<<grid, NTHREADS, SMEM_BYTES>>>(bias, gum);
    softmax_kernel<<<Mx * 4, 128>>>(pads, cb, inputs, W, bias, gum,
                                    ids_out, quant_out, probs_out);
}

// round 8
// speedup vs baseline: 1.3956x; 1.3956x over previous
#include <cuda_runtime.h>
#include <cuda_bf16.h>
#include <cstdint>

// GumbelSoftmaxVectorQuantizer — round 8: 2-term bf16 GEMM
//   logits ≈ Ah·Bh + Ah·Bl   (A rounded to bf16; B split hi/lo)
//   32 MMAs/chunk vs 48 in round 6. Argmax exactness restored by fp32
//   recompute of candidates whenever top-2 gap < 6e-3 (~11 sigma).

static constexpr int Mx = 16384;
static constexpr int Kx = 1024;
static constexpr int Nx = 4096;
static constexpr int Vx = 1024;
static constexpr int Dx = 128;
static constexpr float INV_TAU = 0.5f;

__device__ float g_logits[(size_t)Mx * Nx];
__device__ unsigned short g_Ah[(size_t)Mx * Kx];   // bf16 [M][K]
__device__ unsigned short g_Bh[(size_t)Nx * Kx];   // bf16 [N][K] = W^T hi
__device__ unsigned short g_Bl[(size_t)Nx * Kx];   // bf16 lo

__device__ __forceinline__ uint32_t smem_u32(const void* p) {
    uint32_t a;
    asm("{ .reg .u64 t; cvta.to.shared.u64 t, %1; cvt.u32.u64 %0, t; }" : "=r"(a) : "l"(p));
    return a;
}

// ---------------- K0a: round A to bf16 ----------------
__global__ __launch_bounds__(256)
void split_a_kernel(const float* __restrict__ A) {
    const size_t idx = ((size_t)blockIdx.x * 256 + threadIdx.x) * 8;
    if (idx >= (size_t)Mx * Kx) return;
    float4 a0 = *(const float4*)&A[idx];
    float4 a1 = *(const float4*)&A[idx + 4];
    float v[8] = {a0.x, a0.y, a0.z, a0.w, a1.x, a1.y, a1.z, a1.w};
    unsigned short h[8];
#pragma unroll
    for (int t = 0; t < 8; t++)
        h[t] = __bfloat16_as_ushort(__float2bfloat16(v[t]));
    uint4 uh;
    uh.x = h[0] | ((uint32_t)h[1] << 16); uh.y = h[2] | ((uint32_t)h[3] << 16);
    uh.z = h[4] | ((uint32_t)h[5] << 16); uh.w = h[6] | ((uint32_t)h[7] << 16);
    *(uint4*)&g_Ah[idx] = uh;
}

// ---------------- K0b: split + transpose W ----------------
__global__ __launch_bounds__(256)
void split_w_kernel(const float* __restrict__ W) {
    __shared__ float s[64][65];
    const int ct = blockIdx.y;
    const int n0 = blockIdx.x * 64;
    const int k0 = ct * 64;
    const int tid = threadIdx.x;
    for (int i = tid; i < 1024; i += 256) {
        const int kk = i >> 4, n4 = (i & 15) << 2;
        float4 w = *(const float4*)&W[(size_t)(k0 + kk) * Nx + n0 + n4];
        s[kk][n4] = w.x; s[kk][n4 + 1] = w.y; s[kk][n4 + 2] = w.z; s[kk][n4 + 3] = w.w;
    }
    __syncthreads();
    for (int i = tid; i < 512; i += 256) {
        const int nl = i >> 3, j = (i & 7) << 3;
        unsigned short h[8], l[8];
#pragma unroll
        for (int t = 0; t < 8; t++) {
            float a = s[j + t][nl];
            __nv_bfloat16 hb = __float2bfloat16(a);
            h[t] = __bfloat16_as_ushort(hb);
            l[t] = __bfloat16_as_ushort(__float2bfloat16(a - __bfloat162float(hb)));
        }
        const size_t o = (size_t)(n0 + nl) * Kx + k0 + j;
        uint4 uh, ul;
        uh.x = h[0] | ((uint32_t)h[1] << 16); uh.y = h[2] | ((uint32_t)h[3] << 16);
        uh.z = h[4] | ((uint32_t)h[5] << 16); uh.w = h[6] | ((uint32_t)h[7] << 16);
        ul.x = l[0] | ((uint32_t)l[1] << 16); ul.y = l[2] | ((uint32_t)l[3] << 16);
        ul.z = l[4] | ((uint32_t)l[5] << 16); ul.w = l[6] | ((uint32_t)l[7] << 16);
        *(uint4*)&g_Bh[o] = uh;
        *(uint4*)&g_Bl[o] = ul;
    }
}

// ---------------- K1: mma.sync GEMM ----------------
static constexpr int BK = 32;
static constexpr int STAGES = 4;
static constexpr int RSTRIDE = 40;                  // bf16 per smem row (80B)
static constexpr int OP_BYTES = 128 * RSTRIDE * 2;  // 10240
static constexpr int OFF_AH = 0;
static constexpr int OFF_BH = OP_BYTES;
static constexpr int OFF_BL = 2 * OP_BYTES;
static constexpr int STAGE_BYTES = 3 * OP_BYTES;    // 30720
static constexpr int SMEM_BYTES = STAGES * STAGE_BYTES;  // 122880
static constexpr int NCHUNK = Kx / BK;
static constexpr int NTHREADS = 512;

__device__ __forceinline__ void cp16(uint32_t dst, const void* src) {
    asm volatile("cp.async.cg.shared.global [%0], [%1], 16;" :: "r"(dst), "l"(src) : "memory");
}
__device__ __forceinline__ void cp_commit() {
    asm volatile("cp.async.commit_group;" ::: "memory");
}
__device__ __forceinline__ void cp_wait2() {
    asm volatile("cp.async.wait_group 2;" ::: "memory");
}
__device__ __forceinline__ void ldsm4(uint32_t& r0, uint32_t& r1, uint32_t& r2, uint32_t& r3,
                                      uint32_t addr) {
    asm volatile("ldmatrix.sync.aligned.m8n8.x4.shared.b16 {%0,%1,%2,%3}, [%4];"
                 : "=r"(r0), "=r"(r1), "=r"(r2), "=r"(r3) : "r"(addr));
}
__device__ __forceinline__ void mma_bf16(float* c, const uint32_t* a, const uint32_t* b) {
    asm volatile(
        "mma.sync.aligned.m16n8k16.row.col.f32.bf16.bf16.f32 "
        "{%0,%1,%2,%3}, {%4,%5,%6,%7}, {%8,%9}, {%0,%1,%2,%3};"
        : "+f"(c[0]), "+f"(c[1]), "+f"(c[2]), "+f"(c[3])
        : "r"(a[0]), "r"(a[1]), "r"(a[2]), "r"(a[3]), "r"(b[0]), "r"(b[1]));
}

__global__ __launch_bounds__(NTHREADS, 1)
void gemm_kernel(const float* __restrict__ bias, const float* __restrict__ gum) {
    extern __shared__ char smem[];
    const uint32_t sbase = smem_u32(smem);
    const int tid  = threadIdx.x;
    const int lane = tid & 31;
    const int wid  = tid >> 5;
    const int wm   = wid >> 2;
    const int wn   = wid & 3;
    const int bm   = blockIdx.y * 128;
    const int bn   = blockIdx.x * 128;

    const unsigned short* srcAh = g_Ah + (size_t)bm * Kx;
    const unsigned short* srcBh = g_Bh + (size_t)bn * Kx;
    const unsigned short* srcBl = g_Bl + (size_t)bn * Kx;

    auto issue_stage = [&](int chunk) {
        const int s = chunk & (STAGES - 1);
        const uint32_t stb = sbase + s * STAGE_BYTES;
        const int r = (tid >> 2) & 127;
        const int c = tid & 3;
        const uint32_t doff = (uint32_t)(r * RSTRIDE * 2 + c * 16);
        const size_t soff = (size_t)r * Kx + chunk * BK + c * 8;
        cp16(stb + OFF_AH + doff, srcAh + soff);
        cp16(stb + OFF_BH + doff, srcBh + soff);
        cp16(stb + OFF_BL + doff, srcBl + soff);
        cp_commit();
    };

    float acc[2][4][4];
#pragma unroll
    for (int i = 0; i < 2; i++)
#pragma unroll
        for (int j = 0; j < 4; j++)
#pragma unroll
            for (int q = 0; q < 4; q++) acc[i][j][q] = 0.f;

    issue_stage(0); issue_stage(1); issue_stage(2);

    const int lrow = lane & 15;
    const int lcol = (lane >> 4) * 8;

#pragma unroll 1
    for (int ch = 0; ch < NCHUNK; ch++) {
        cp_wait2();
        __syncthreads();
        if (ch + 3 < NCHUNK) issue_stage(ch + 3);

        const uint32_t stb = sbase + (ch & (STAGES - 1)) * STAGE_BYTES;
        const uint32_t aho = stb + OFF_AH;
        const uint32_t bho = stb + OFF_BH;
        const uint32_t blo = stb + OFF_BL;

#pragma unroll
        for (int ks = 0; ks < 2; ks++) {
            const int kk = ks * 16;
            uint32_t ah[2][4], bh[4][2], bl[4][2];
#pragma unroll
            for (int mf = 0; mf < 2; mf++) {
                const int row = wm * 32 + mf * 16 + lrow;
                const uint32_t off = (uint32_t)(row * RSTRIDE + kk + lcol) * 2;
                ldsm4(ah[mf][0], ah[mf][1], ah[mf][2], ah[mf][3], aho + off);
            }
#pragma unroll
            for (int np = 0; np < 2; np++) {
                const int row = wn * 32 + np * 16 + lrow;
                const uint32_t off = (uint32_t)(row * RSTRIDE + kk + lcol) * 2;
                uint32_t r0, r1, r2, r3;
                ldsm4(r0, r1, r2, r3, bho + off);
                bh[2 * np][0] = r0; bh[2 * np][1] = r2;
                bh[2 * np + 1][0] = r1; bh[2 * np + 1][1] = r3;
                ldsm4(r0, r1, r2, r3, blo + off);
                bl[2 * np][0] = r0; bl[2 * np][1] = r2;
                bl[2 * np + 1][0] = r1; bl[2 * np + 1][1] = r3;
            }
            // product-outer ordering: 8 independent accumulators between reuse
#pragma unroll
            for (int mf = 0; mf < 2; mf++)
#pragma unroll
                for (int nf = 0; nf < 4; nf++)
                    mma_bf16(acc[mf][nf], ah[mf], bh[nf]);
#pragma unroll
            for (int mf = 0; mf < 2; mf++)
#pragma unroll
                for (int nf = 0; nf < 4; nf++)
                    mma_bf16(acc[mf][nf], ah[mf], bl[nf]);
        }
        __syncthreads();
    }

    // epilogue: (acc + bias + gumbel) * INV_TAU -> g_logits
    const int er = lane >> 2;
    const int ec = (lane & 3) * 2;
#pragma unroll
    for (int mf = 0; mf < 2; mf++) {
#pragma unroll
        for (int nf = 0; nf < 4; nf++) {
            const int col = bn + wn * 32 + nf * 8 + ec;
            const float2 bb = *(const float2*)&bias[col];
#pragma unroll
            for (int h = 0; h < 2; h++) {
                const int row = bm + wm * 32 + mf * 16 + er + h * 8;
                const size_t go = (size_t)row * Nx + col;
                const float2 g = *(const float2*)&gum[go];
                float2 o;
                o.x = (acc[mf][nf][2 * h]     + bb.x + g.x) * INV_TAU;
                o.y = (acc[mf][nf][2 * h + 1] + bb.y + g.y) * INV_TAU;
                *(float2*)&g_logits[go] = o;
            }
        }
    }
}

// ---------------- K2: softmax + argmax(top2 + exact fixup) ----------------
__global__ __launch_bounds__(128)
void softmax_kernel(const int*   __restrict__ pads,
                    const float* __restrict__ codebook,
                    const float* __restrict__ A,
                    const float* __restrict__ W,
                    const float* __restrict__ bias,
                    const float* __restrict__ gum,
                    float*       __restrict__ ids_out,
                    float*       __restrict__ quant_out,
                    float*       __restrict__ probs_out)
{
    const int grp  = blockIdx.x;
    const int row  = grp >> 2;
    const int g    = grp & 3;
    const int tid  = threadIdx.x;
    const int lane = tid & 31;
    const int warp = tid >> 5;

    const float* base = g_logits + (size_t)grp * Vx;

    float v[8];
    *(float4*)&v[0] = *(const float4*)&base[tid * 8];
    *(float4*)&v[4] = *(const float4*)&base[tid * 8 + 4];

    float m1 = v[0], m2 = -3.4e38f;
    int i1 = tid * 8, i2 = -1;
#pragma unroll
    for (int j = 1; j < 8; j++) {
        const int ii = tid * 8 + j;
        if (v[j] > m1) { m2 = m1; i2 = i1; m1 = v[j]; i1 = ii; }
        else if (v[j] > m2) { m2 = v[j]; i2 = ii; }
    }
#pragma unroll
    for (int off = 16; off > 0; off >>= 1) {
        float o1 = __shfl_down_sync(0xffffffffu, m1, off);
        int   oi1 = __shfl_down_sync(0xffffffffu, i1, off);
        float o2 = __shfl_down_sync(0xffffffffu, m2, off);
        int   oi2 = __shfl_down_sync(0xffffffffu, i2, off);
        if (o1 > m1 || (o1 == m1 && oi1 < i1)) {
            float t2 = (m1 > o2 || (m1 == o2 && i1 < oi2)) ? m1 : o2;
            int   ti2 = (m1 > o2 || (m1 == o2 && i1 < oi2)) ? i1 : oi2;
            m1 = o1; i1 = oi1; m2 = t2; i2 = ti2;
        } else {
            if (o1 > m2 || (o1 == m2 && oi1 < i2)) { m2 = o1; i2 = oi1; }
        }
    }

    __shared__ float sw1[4], sw2[4], ssum[4];
    __shared__ int   si1[4], si2[4];
    __shared__ float red_m, red_s, sfix[2];
    __shared__ int   red_i, cand1, cand2, need_fix;

    if (lane == 0) { sw1[warp] = m1; si1[warp] = i1; sw2[warp] = m2; si2[warp] = i2; }
    __syncthreads();
    if (tid == 0) {
        float b1 = sw1[0], b2 = sw2[0]; int j1 = si1[0], j2 = si2[0];
        for (int w = 1; w < 4; w++) {
            float o1 = sw1[w], o2 = sw2[w]; int oi1 = si1[w], oi2 = si2[w];
            if (o1 > b1 || (o1 == b1 && oi1 < j1)) {
                float t2 = (b1 > o2 || (b1 == o2 && j1 < oi2)) ? b1 : o2;
                int   ti2 = (b1 > o2 || (b1 == o2 && j1 < oi2)) ? j1 : oi2;
                b1 = o1; j1 = oi1; b2 = t2; j2 = ti2;
            } else if (o1 > b2 || (o1 == b2 && oi1 < j2)) { b2 = o1; j2 = oi1; }
        }
        red_m = b1; red_i = j1; cand1 = j1; cand2 = j2;
        need_fix = (b1 - b2 < 6e-3f) ? 1 : 0;
    }
    __syncthreads();

    const int pad = pads[row];

    if (need_fix && !pad) {
        const float* arow = A + (size_t)row * Kx;
        for (int cidx = 0; cidx < 2; cidx++) {
            const int vv = (cidx == 0) ? cand1 : cand2;
            const int col = (g << 10) + vv;
            float part = 0.f;
#pragma unroll
            for (int j = 0; j < 8; j++) {
                const int k = tid * 8 + j;
                part = fmaf(arow[k], W[(size_t)k * Nx + col], part);
            }
#pragma unroll
            for (int off = 16; off > 0; off >>= 1)
                part += __shfl_down_sync(0xffffffffu, part, off);
            if (lane == 0) ssum[warp] = part;
            __syncthreads();
            if (tid == 0) {
                float tot = ssum[0] + ssum[1] + ssum[2] + ssum[3];
                sfix[cidx] = (tot + bias[col] + gum[(size_t)grp * Vx + vv]) * INV_TAU;
            }
            __syncthreads();
        }
        if (tid == 0) {
            const float v1 = sfix[0], v2 = sfix[1];
            red_i = (v2 > v1 || (v2 == v1 && cand2 < cand1)) ? cand2 : cand1;
        }
        __syncthreads();
    }

    const float mx = red_m;
    float e[8]; float s = 0.f;
#pragma unroll
    for (int j = 0; j < 8; j++) { e[j] = __expf(v[j] - mx); s += e[j]; }
#pragma unroll
    for (int off = 16; off > 0; off >>= 1)
        s += __shfl_down_sync(0xffffffffu, s, off);
    if (lane == 0) ssum[warp] = s;
    __syncthreads();
    if (tid == 0) red_s = ssum[0] + ssum[1] + ssum[2] + ssum[3];
    __syncthreads();

    const float inv = pad ? 0.f : (1.f / red_s);
    float4 p0, p1;
    p0.x = e[0] * inv; p0.y = e[1] * inv; p0.z = e[2] * inv; p0.w = e[3] * inv;
    p1.x = e[4] * inv; p1.y = e[5] * inv; p1.z = e[6] * inv; p1.w = e[7] * inv;
    *(float4*)&probs_out[(size_t)grp * Vx + tid * 8]     = p0;
    *(float4*)&probs_out[(size_t)grp * Vx + tid * 8 + 4] = p1;

    const int id = red_i;
    const float q = pad ? 0.f : codebook[(((g << 10) + id) << 7) + tid];
    quant_out[(size_t)row * (4 * Dx) + g * Dx + tid] = q;
    if (tid == 0) ids_out[grp] = pad ? -1.0f : (float)id;
}

// ---------------- launch ----------------
extern "C" void kernel_launch(void* const* d_in, const int* in_sizes, int n_in,
                              void* d_out, int out_size)
{
    const float* inputs = (const float*)d_in[0];
    const int*   pads   = (const int*)  d_in[1];
    const float* gum    = (const float*)d_in[2];
    const float* W      = (const float*)d_in[3];
    const float* bias   = (const float*)d_in[4];
    const float* cb     = (const float*)d_in[5];

    float* out       = (float*)d_out;
    float* ids_out   = out;
    float* quant_out = out + (size_t)Mx * 4;
    float* probs_out = quant_out + (size_t)Mx * 4 * Dx;

    cudaFuncSetAttribute(gemm_kernel, cudaFuncAttributeMaxDynamicSharedMemorySize, SMEM_BYTES);

    split_a_kernel<<<(Mx * Kx / 8 + 255) / 256, 256>>>(inputs);
    dim3 wg(Nx / 64, Kx / 64);
    split_w_kernel<<<wg, 256>>>(W);
    dim3 grid(Nx / 128, Mx / 128);
    gemm_kernel<<<grid, NTHREADS, SMEM_BYTES>>>(bias, gum);
    softmax_kernel<<<Mx * 4, 128>>>(pads, cb, inputs, W, bias, gum,
                                    ids_out, quant_out, probs_out);
}

// round 9
// speedup vs baseline: 2.1702x; 1.5550x over previous
#include <cuda_runtime.h>
#include <cuda_fp16.h>
#include <cstdint>

// GumbelSoftmaxVectorQuantizer — round 9: single-term fp16 GEMM
//   logits ≈ fp16(A) · fp16(W^T)  — fp16 has 11 mantissa bits, products are
//   exact in fp32 accum; logit err ~4e-4 -> rel_err ~1.5e-4 (7x margin).
//   16 MMAs/chunk (half of round 8). Argmax exactness via fp32 recompute
//   of top-2 candidates whenever gap < 3e-3 (~11 sigma).

static constexpr int Mx = 16384;
static constexpr int Kx = 1024;
static constexpr int Nx = 4096;
static constexpr int Vx = 1024;
static constexpr int Dx = 128;
static constexpr float INV_TAU = 0.5f;

__device__ float g_logits[(size_t)Mx * Nx];
__device__ unsigned short g_Ah[(size_t)Mx * Kx];   // fp16 [M][K]
__device__ unsigned short g_Bh[(size_t)Nx * Kx];   // fp16 [N][K] = W^T

__device__ __forceinline__ uint32_t smem_u32(const void* p) {
    uint32_t a;
    asm("{ .reg .u64 t; cvta.to.shared.u64 t, %1; cvt.u32.u64 %0, t; }" : "=r"(a) : "l"(p));
    return a;
}

// ---------------- K0a: convert A to fp16 ----------------
__global__ __launch_bounds__(256)
void split_a_kernel(const float* __restrict__ A) {
    const size_t idx = ((size_t)blockIdx.x * 256 + threadIdx.x) * 8;
    if (idx >= (size_t)Mx * Kx) return;
    float4 a0 = *(const float4*)&A[idx];
    float4 a1 = *(const float4*)&A[idx + 4];
    float v[8] = {a0.x, a0.y, a0.z, a0.w, a1.x, a1.y, a1.z, a1.w};
    unsigned short h[8];
#pragma unroll
    for (int t = 0; t < 8; t++)
        h[t] = __half_as_ushort(__float2half_rn(v[t]));
    uint4 uh;
    uh.x = h[0] | ((uint32_t)h[1] << 16); uh.y = h[2] | ((uint32_t)h[3] << 16);
    uh.z = h[4] | ((uint32_t)h[5] << 16); uh.w = h[6] | ((uint32_t)h[7] << 16);
    *(uint4*)&g_Ah[idx] = uh;
}

// ---------------- K0b: transpose + convert W ----------------
__global__ __launch_bounds__(256)
void split_w_kernel(const float* __restrict__ W) {
    __shared__ float s[64][65];
    const int ct = blockIdx.y;
    const int n0 = blockIdx.x * 64;
    const int k0 = ct * 64;
    const int tid = threadIdx.x;
    for (int i = tid; i < 1024; i += 256) {
        const int kk = i >> 4, n4 = (i & 15) << 2;
        float4 w = *(const float4*)&W[(size_t)(k0 + kk) * Nx + n0 + n4];
        s[kk][n4] = w.x; s[kk][n4 + 1] = w.y; s[kk][n4 + 2] = w.z; s[kk][n4 + 3] = w.w;
    }
    __syncthreads();
    for (int i = tid; i < 512; i += 256) {
        const int nl = i >> 3, j = (i & 7) << 3;
        unsigned short h[8];
#pragma unroll
        for (int t = 0; t < 8; t++)
            h[t] = __half_as_ushort(__float2half_rn(s[j + t][nl]));
        const size_t o = (size_t)(n0 + nl) * Kx + k0 + j;
        uint4 uh;
        uh.x = h[0] | ((uint32_t)h[1] << 16); uh.y = h[2] | ((uint32_t)h[3] << 16);
        uh.z = h[4] | ((uint32_t)h[5] << 16); uh.w = h[6] | ((uint32_t)h[7] << 16);
        *(uint4*)&g_Bh[o] = uh;
    }
}

// ---------------- K1: mma.sync fp16 GEMM ----------------
static constexpr int BK = 32;
static constexpr int STAGES = 4;
static constexpr int RSTRIDE = 40;                  // fp16 per smem row (80B)
static constexpr int OP_BYTES = 128 * RSTRIDE * 2;  // 10240
static constexpr int OFF_AH = 0;
static constexpr int OFF_BH = OP_BYTES;
static constexpr int STAGE_BYTES = 2 * OP_BYTES;    // 20480
static constexpr int SMEM_BYTES = STAGES * STAGE_BYTES;  // 81920
static constexpr int NCHUNK = Kx / BK;
static constexpr int NTHREADS = 512;

__device__ __forceinline__ void cp16(uint32_t dst, const void* src) {
    asm volatile("cp.async.cg.shared.global [%0], [%1], 16;" :: "r"(dst), "l"(src) : "memory");
}
__device__ __forceinline__ void cp_commit() {
    asm volatile("cp.async.commit_group;" ::: "memory");
}
__device__ __forceinline__ void cp_wait2() {
    asm volatile("cp.async.wait_group 2;" ::: "memory");
}
__device__ __forceinline__ void ldsm4(uint32_t& r0, uint32_t& r1, uint32_t& r2, uint32_t& r3,
                                      uint32_t addr) {
    asm volatile("ldmatrix.sync.aligned.m8n8.x4.shared.b16 {%0,%1,%2,%3}, [%4];"
                 : "=r"(r0), "=r"(r1), "=r"(r2), "=r"(r3) : "r"(addr));
}
__device__ __forceinline__ void mma_f16(float* c, const uint32_t* a, const uint32_t* b) {
    asm volatile(
        "mma.sync.aligned.m16n8k16.row.col.f32.f16.f16.f32 "
        "{%0,%1,%2,%3}, {%4,%5,%6,%7}, {%8,%9}, {%0,%1,%2,%3};"
        : "+f"(c[0]), "+f"(c[1]), "+f"(c[2]), "+f"(c[3])
        : "r"(a[0]), "r"(a[1]), "r"(a[2]), "r"(a[3]), "r"(b[0]), "r"(b[1]));
}

__global__ __launch_bounds__(NTHREADS, 1)
void gemm_kernel(const float* __restrict__ bias, const float* __restrict__ gum) {
    extern __shared__ char smem[];
    const uint32_t sbase = smem_u32(smem);
    const int tid  = threadIdx.x;
    const int lane = tid & 31;
    const int wid  = tid >> 5;
    const int wm   = wid >> 2;
    const int wn   = wid & 3;
    const int bm   = blockIdx.y * 128;
    const int bn   = blockIdx.x * 128;

    const unsigned short* srcAh = g_Ah + (size_t)bm * Kx;
    const unsigned short* srcBh = g_Bh + (size_t)bn * Kx;

    auto issue_stage = [&](int chunk) {
        const int s = chunk & (STAGES - 1);
        const uint32_t stb = sbase + s * STAGE_BYTES;
        const int r = (tid >> 2) & 127;
        const int c = tid & 3;
        const uint32_t doff = (uint32_t)(r * RSTRIDE * 2 + c * 16);
        const size_t soff = (size_t)r * Kx + chunk * BK + c * 8;
        cp16(stb + OFF_AH + doff, srcAh + soff);
        cp16(stb + OFF_BH + doff, srcBh + soff);
        cp_commit();
    };

    float acc[2][4][4];
#pragma unroll
    for (int i = 0; i < 2; i++)
#pragma unroll
        for (int j = 0; j < 4; j++)
#pragma unroll
            for (int q = 0; q < 4; q++) acc[i][j][q] = 0.f;

    issue_stage(0); issue_stage(1); issue_stage(2);

    const int lrow = lane & 15;
    const int lcol = (lane >> 4) * 8;

#pragma unroll 1
    for (int ch = 0; ch < NCHUNK; ch++) {
        cp_wait2();
        __syncthreads();
        if (ch + 3 < NCHUNK) issue_stage(ch + 3);

        const uint32_t stb = sbase + (ch & (STAGES - 1)) * STAGE_BYTES;
        const uint32_t aho = stb + OFF_AH;
        const uint32_t bho = stb + OFF_BH;

#pragma unroll
        for (int ks = 0; ks < 2; ks++) {
            const int kk = ks * 16;
            uint32_t ah[2][4], bh[4][2];
#pragma unroll
            for (int mf = 0; mf < 2; mf++) {
                const int row = wm * 32 + mf * 16 + lrow;
                const uint32_t off = (uint32_t)(row * RSTRIDE + kk + lcol) * 2;
                ldsm4(ah[mf][0], ah[mf][1], ah[mf][2], ah[mf][3], aho + off);
            }
#pragma unroll
            for (int np = 0; np < 2; np++) {
                const int row = wn * 32 + np * 16 + lrow;
                const uint32_t off = (uint32_t)(row * RSTRIDE + kk + lcol) * 2;
                uint32_t r0, r1, r2, r3;
                ldsm4(r0, r1, r2, r3, bho + off);
                bh[2 * np][0] = r0; bh[2 * np][1] = r2;
                bh[2 * np + 1][0] = r1; bh[2 * np + 1][1] = r3;
            }
#pragma unroll
            for (int mf = 0; mf < 2; mf++)
#pragma unroll
                for (int nf = 0; nf < 4; nf++)
                    mma_f16(acc[mf][nf], ah[mf], bh[nf]);
        }
        __syncthreads();
    }

    // epilogue: (acc + bias + gumbel) * INV_TAU -> g_logits
    const int er = lane >> 2;
    const int ec = (lane & 3) * 2;
#pragma unroll
    for (int mf = 0; mf < 2; mf++) {
#pragma unroll
        for (int nf = 0; nf < 4; nf++) {
            const int col = bn + wn * 32 + nf * 8 + ec;
            const float2 bb = *(const float2*)&bias[col];
#pragma unroll
            for (int h = 0; h < 2; h++) {
                const int row = bm + wm * 32 + mf * 16 + er + h * 8;
                const size_t go = (size_t)row * Nx + col;
                const float2 g = *(const float2*)&gum[go];
                float2 o;
                o.x = (acc[mf][nf][2 * h]     + bb.x + g.x) * INV_TAU;
                o.y = (acc[mf][nf][2 * h + 1] + bb.y + g.y) * INV_TAU;
                *(float2*)&g_logits[go] = o;
            }
        }
    }
}

// ---------------- K2: softmax + argmax(top2 + exact fixup) ----------------
__global__ __launch_bounds__(128)
void softmax_kernel(const int*   __restrict__ pads,
                    const float* __restrict__ codebook,
                    const float* __restrict__ A,
                    const float* __restrict__ W,
                    const float* __restrict__ bias,
                    const float* __restrict__ gum,
                    float*       __restrict__ ids_out,
                    float*       __restrict__ quant_out,
                    float*       __restrict__ probs_out)
{
    const int grp  = blockIdx.x;
    const int row  = grp >> 2;
    const int g    = grp & 3;
    const int tid  = threadIdx.x;
    const int lane = tid & 31;
    const int warp = tid >> 5;

    const float* base = g_logits + (size_t)grp * Vx;

    float v[8];
    *(float4*)&v[0] = *(const float4*)&base[tid * 8];
    *(float4*)&v[4] = *(const float4*)&base[tid * 8 + 4];

    float m1 = v[0], m2 = -3.4e38f;
    int i1 = tid * 8, i2 = -1;
#pragma unroll
    for (int j = 1; j < 8; j++) {
        const int ii = tid * 8 + j;
        if (v[j] > m1) { m2 = m1; i2 = i1; m1 = v[j]; i1 = ii; }
        else if (v[j] > m2) { m2 = v[j]; i2 = ii; }
    }
#pragma unroll
    for (int off = 16; off > 0; off >>= 1) {
        float o1 = __shfl_down_sync(0xffffffffu, m1, off);
        int   oi1 = __shfl_down_sync(0xffffffffu, i1, off);
        float o2 = __shfl_down_sync(0xffffffffu, m2, off);
        int   oi2 = __shfl_down_sync(0xffffffffu, i2, off);
        if (o1 > m1 || (o1 == m1 && oi1 < i1)) {
            float t2 = (m1 > o2 || (m1 == o2 && i1 < oi2)) ? m1 : o2;
            int   ti2 = (m1 > o2 || (m1 == o2 && i1 < oi2)) ? i1 : oi2;
            m1 = o1; i1 = oi1; m2 = t2; i2 = ti2;
        } else {
            if (o1 > m2 || (o1 == m2 && oi1 < i2)) { m2 = o1; i2 = oi1; }
        }
    }

    __shared__ float sw1[4], sw2[4], ssum[4];
    __shared__ int   si1[4], si2[4];
    __shared__ float red_m, red_s, sfix[2];
    __shared__ int   red_i, cand1, cand2, need_fix;

    if (lane == 0) { sw1[warp] = m1; si1[warp] = i1; sw2[warp] = m2; si2[warp] = i2; }
    __syncthreads();
    if (tid == 0) {
        float b1 = sw1[0], b2 = sw2[0]; int j1 = si1[0], j2 = si2[0];
        for (int w = 1; w < 4; w++) {
            float o1 = sw1[w], o2 = sw2[w]; int oi1 = si1[w], oi2 = si2[w];
            if (o1 > b1 || (o1 == b1 && oi1 < j1)) {
                float t2 = (b1 > o2 || (b1 == o2 && j1 < oi2)) ? b1 : o2;
                int   ti2 = (b1 > o2 || (b1 == o2 && j1 < oi2)) ? j1 : oi2;
                b1 = o1; j1 = oi1; b2 = t2; j2 = ti2;
            } else if (o1 > b2 || (o1 == b2 && oi1 < j2)) { b2 = o1; j2 = oi1; }
        }
        red_m = b1; red_i = j1; cand1 = j1; cand2 = j2;
        need_fix = (b1 - b2 < 3e-3f) ? 1 : 0;
    }
    __syncthreads();

    const int pad = pads[row];

    if (need_fix && !pad) {
        const float* arow = A + (size_t)row * Kx;
        for (int cidx = 0; cidx < 2; cidx++) {
            const int vv = (cidx == 0) ? cand1 : cand2;
            const int col = (g << 10) + vv;
            float part = 0.f;
#pragma unroll
            for (int j = 0; j < 8; j++) {
                const int k = tid * 8 + j;
                part = fmaf(arow[k], W[(size_t)k * Nx + col], part);
            }
#pragma unroll
            for (int off = 16; off > 0; off >>= 1)
                part += __shfl_down_sync(0xffffffffu, part, off);
            if (lane == 0) ssum[warp] = part;
            __syncthreads();
            if (tid == 0) {
                float tot = ssum[0] + ssum[1] + ssum[2] + ssum[3];
                sfix[cidx] = (tot + bias[col] + gum[(size_t)grp * Vx + vv]) * INV_TAU;
            }
            __syncthreads();
        }
        if (tid == 0) {
            const float v1 = sfix[0], v2 = sfix[1];
            red_i = (v2 > v1 || (v2 == v1 && cand2 < cand1)) ? cand2 : cand1;
        }
        __syncthreads();
    }

    const float mx = red_m;
    float e[8]; float s = 0.f;
#pragma unroll
    for (int j = 0; j < 8; j++) { e[j] = __expf(v[j] - mx); s += e[j]; }
#pragma unroll
    for (int off = 16; off > 0; off >>= 1)
        s += __shfl_down_sync(0xffffffffu, s, off);
    if (lane == 0) ssum[warp] = s;
    __syncthreads();
    if (tid == 0) red_s = ssum[0] + ssum[1] + ssum[2] + ssum[3];
    __syncthreads();

    const float inv = pad ? 0.f : (1.f / red_s);
    float4 p0, p1;
    p0.x = e[0] * inv; p0.y = e[1] * inv; p0.z = e[2] * inv; p0.w = e[3] * inv;
    p1.x = e[4] * inv; p1.y = e[5] * inv; p1.z = e[6] * inv; p1.w = e[7] * inv;
    *(float4*)&probs_out[(size_t)grp * Vx + tid * 8]     = p0;
    *(float4*)&probs_out[(size_t)grp * Vx + tid * 8 + 4] = p1;

    const int id = red_i;
    const float q = pad ? 0.f : codebook[(((g << 10) + id) << 7) + tid];
    quant_out[(size_t)row * (4 * Dx) + g * Dx + tid] = q;
    if (tid == 0) ids_out[grp] = pad ? -1.0f : (float)id;
}

// ---------------- launch ----------------
extern "C" void kernel_launch(void* const* d_in, const int* in_sizes, int n_in,
                              void* d_out, int out_size)
{
    const float* inputs = (const float*)d_in[0];
    const int*   pads   = (const int*)  d_in[1];
    const float* gum    = (const float*)d_in[2];
    const float* W      = (const float*)d_in[3];
    const float* bias   = (const float*)d_in[4];
    const float* cb     = (const float*)d_in[5];

    float* out       = (float*)d_out;
    float* ids_out   = out;
    float* quant_out = out + (size_t)Mx * 4;
    float* probs_out = quant_out + (size_t)Mx * 4 * Dx;

    cudaFuncSetAttribute(gemm_kernel, cudaFuncAttributeMaxDynamicSharedMemorySize, SMEM_BYTES);

    split_a_kernel<<<(Mx * Kx / 8 + 255) / 256, 256>>>(inputs);
    dim3 wg(Nx / 64, Kx / 64);
    split_w_kernel<<<wg, 256>>>(W);
    dim3 grid(Nx / 128, Mx / 128);
    gemm_kernel<<<grid, NTHREADS, SMEM_BYTES>>>(bias, gum);
    softmax_kernel<<<Mx * 4, 128>>>(pads, cb, inputs, W, bias, gum,
                                    ids_out, quant_out, probs_out);
}